// round 1
// baseline (speedup 1.0000x reference)
#include <cuda_runtime.h>
#include <math.h>

// Shapes: B=16, H=W=32 (N=1024), C=512, GROUPS=32 (16 ch/group)
// Scratch (static __device__, no allocation):
__device__ float g_xn[16u*1024u*512u];
__device__ float g_q [16u*1024u*512u];
__device__ float g_k [16u*1024u*512u];
__device__ float g_v [16u*1024u*512u];
__device__ float g_o [16u*1024u*512u];
__device__ float g_s [16u*1024u*1024u];

// ---------------- GroupNorm: one block per (batch, group) ----------------
__global__ void groupnorm_kernel(const float* __restrict__ x,
                                 const float* __restrict__ gamma,
                                 const float* __restrict__ beta,
                                 float* __restrict__ out) {
    const int b = blockIdx.x >> 5;   // 16 batches
    const int g = blockIdx.x & 31;   // 32 groups
    const float* xb = x + (size_t)b * 1024 * 512 + g * 16;
    float s1 = 0.f, s2 = 0.f;
    for (int i = threadIdx.x; i < 16384; i += 256) {
        int n = i >> 4, c = i & 15;
        float v = xb[(size_t)n * 512 + c];
        s1 += v; s2 += v * v;
    }
    __shared__ float r1[256], r2[256];
    r1[threadIdx.x] = s1; r2[threadIdx.x] = s2;
    __syncthreads();
    for (int off = 128; off > 0; off >>= 1) {
        if (threadIdx.x < off) {
            r1[threadIdx.x] += r1[threadIdx.x + off];
            r2[threadIdx.x] += r2[threadIdx.x + off];
        }
        __syncthreads();
    }
    const float mean = r1[0] * (1.f / 16384.f);
    const float var  = r2[0] * (1.f / 16384.f) - mean * mean;
    const float inv  = rsqrtf(var + 1e-3f);
    float* ob = out + (size_t)b * 1024 * 512 + g * 16;
    for (int i = threadIdx.x; i < 16384; i += 256) {
        int n = i >> 4, c = i & 15;
        int ch = g * 16 + c;
        float v = xb[(size_t)n * 512 + c];
        ob[(size_t)n * 512 + c] = (v - mean) * inv * gamma[ch] + beta[ch];
    }
}

// ---------------- Generic 64x64x16 fp32 tiled GEMM ----------------
// C[M,N] = alpha * A[M,K] @ op(B) (+bias) (+res), batched via blockIdx.z.
// TRANSB=0: B is [K,N] row-major. TRANSB=1: B is [N,K] row-major (B @ B^T form).
template<int TRANSB, int HAS_BIAS, int HAS_RES>
__global__ void gemm64(const float* __restrict__ A, const float* __restrict__ B,
                       const float* __restrict__ bias, const float* __restrict__ res,
                       float* __restrict__ C, int M, int N, int K, float alpha,
                       size_t sA, size_t sB, size_t sC) {
    __shared__ float As[16][64];
    __shared__ float Bs[16][64];
    const int tid = threadIdx.x;
    const int tx = tid & 15, ty = tid >> 4;
    const int rowBase = blockIdx.y * 64;
    const int colBase = blockIdx.x * 64;
    A += (size_t)blockIdx.z * sA;
    B += (size_t)blockIdx.z * sB;
    C += (size_t)blockIdx.z * sC;

    float acc[4][4] = {};
    const int ar = tid >> 2, as = tid & 3;   // A / trans-B loader: row, float4 segment
    const int br = tid >> 4, bs = tid & 15;  // NN B loader

    for (int k0 = 0; k0 < K; k0 += 16) {
        float4 av = *(const float4*)(A + (size_t)(rowBase + ar) * K + k0 + as * 4);
        As[as * 4 + 0][ar] = av.x; As[as * 4 + 1][ar] = av.y;
        As[as * 4 + 2][ar] = av.z; As[as * 4 + 3][ar] = av.w;
        if (TRANSB) {
            float4 bv = *(const float4*)(B + (size_t)(colBase + ar) * K + k0 + as * 4);
            Bs[as * 4 + 0][ar] = bv.x; Bs[as * 4 + 1][ar] = bv.y;
            Bs[as * 4 + 2][ar] = bv.z; Bs[as * 4 + 3][ar] = bv.w;
        } else {
            float4 bv = *(const float4*)(B + (size_t)(k0 + br) * N + colBase + bs * 4);
            *(float4*)&Bs[br][bs * 4] = bv;
        }
        __syncthreads();
#pragma unroll
        for (int k = 0; k < 16; ++k) {
            float4 a4 = *(const float4*)&As[k][ty * 4];
            float4 b4 = *(const float4*)&Bs[k][tx * 4];
            float a[4] = {a4.x, a4.y, a4.z, a4.w};
            float b[4] = {b4.x, b4.y, b4.z, b4.w};
#pragma unroll
            for (int i = 0; i < 4; i++)
#pragma unroll
                for (int j = 0; j < 4; j++)
                    acc[i][j] += a[i] * b[j];
        }
        __syncthreads();
    }

#pragma unroll
    for (int i = 0; i < 4; i++) {
        const int row = rowBase + ty * 4 + i;
        const int col0 = colBase + tx * 4;
        float4 v;
        v.x = acc[i][0] * alpha; v.y = acc[i][1] * alpha;
        v.z = acc[i][2] * alpha; v.w = acc[i][3] * alpha;
        if (HAS_BIAS) {
            v.x += bias[col0 + 0]; v.y += bias[col0 + 1];
            v.z += bias[col0 + 2]; v.w += bias[col0 + 3];
        }
        if (HAS_RES) {
            float4 r = *(const float4*)(res + (size_t)row * N + col0);
            v.x += r.x; v.y += r.y; v.z += r.z; v.w += r.w;
        }
        *(float4*)(C + (size_t)row * N + col0) = v;
    }
}

// ---------------- Row softmax over 1024 elements ----------------
__global__ void softmax1024(float* __restrict__ S) {
    float* p = S + (size_t)blockIdx.x * 1024;
    const int t = threadIdx.x;
    float4 x4 = ((float4*)p)[t];
    float m = fmaxf(fmaxf(x4.x, x4.y), fmaxf(x4.z, x4.w));
    __shared__ float red[256];
    red[t] = m;
    __syncthreads();
    for (int off = 128; off > 0; off >>= 1) {
        if (t < off) red[t] = fmaxf(red[t], red[t + off]);
        __syncthreads();
    }
    m = red[0];
    __syncthreads();
    x4.x = expf(x4.x - m); x4.y = expf(x4.y - m);
    x4.z = expf(x4.z - m); x4.w = expf(x4.w - m);
    red[t] = x4.x + x4.y + x4.z + x4.w;
    __syncthreads();
    for (int off = 128; off > 0; off >>= 1) {
        if (t < off) red[t] += red[t + off];
        __syncthreads();
    }
    const float inv = 1.f / red[0];
    x4.x *= inv; x4.y *= inv; x4.z *= inv; x4.w *= inv;
    ((float4*)p)[t] = x4;
}

extern "C" void kernel_launch(void* const* d_in, const int* in_sizes, int n_in,
                              void* d_out, int out_size) {
    const float* x     = (const float*)d_in[0];
    const float* gamma = (const float*)d_in[1];
    const float* beta  = (const float*)d_in[2];
    const float* wq    = (const float*)d_in[3];
    const float* bq    = (const float*)d_in[4];
    const float* wk    = (const float*)d_in[5];
    const float* bk    = (const float*)d_in[6];
    const float* wv    = (const float*)d_in[7];
    const float* bv    = (const float*)d_in[8];
    const float* wp    = (const float*)d_in[9];
    const float* bp    = (const float*)d_in[10];
    float* out = (float*)d_out;

    float *xn, *q, *k, *v, *o, *s;
    cudaGetSymbolAddress((void**)&xn, g_xn);
    cudaGetSymbolAddress((void**)&q,  g_q);
    cudaGetSymbolAddress((void**)&k,  g_k);
    cudaGetSymbolAddress((void**)&v,  g_v);
    cudaGetSymbolAddress((void**)&o,  g_o);
    cudaGetSymbolAddress((void**)&s,  g_s);

    const float scale = 0.044194173824159216f;  // 512^-0.5
    const size_t sQK = 1024u * 512u;            // per-batch Q/K/V/O stride
    const size_t sS  = 1024u * 1024u;           // per-batch scores stride

    // 1) GroupNorm
    groupnorm_kernel<<<512, 256>>>(x, gamma, beta, xn);
    // 2) Q, K, V projections: [16384,512] @ [512,512] + bias
    gemm64<0,1,0><<<dim3(8, 256, 1), 256>>>(xn, wq, bq, nullptr, q, 16384, 512, 512, 1.f, 0, 0, 0);
    gemm64<0,1,0><<<dim3(8, 256, 1), 256>>>(xn, wk, bk, nullptr, k, 16384, 512, 512, 1.f, 0, 0, 0);
    gemm64<0,1,0><<<dim3(8, 256, 1), 256>>>(xn, wv, bv, nullptr, v, 16384, 512, 512, 1.f, 0, 0, 0);
    // 3) scores = scale * Q @ K^T  (batched, NT)
    gemm64<1,0,0><<<dim3(16, 16, 16), 256>>>(q, k, nullptr, nullptr, s, 1024, 1024, 512, scale, sQK, sQK, sS);
    // 4) softmax rows
    softmax1024<<<16384, 256>>>(s);
    // 5) O = P @ V (batched, NN)
    gemm64<0,0,0><<<dim3(8, 16, 16), 256>>>(s, v, nullptr, nullptr, o, 1024, 512, 1024, 1.f, sS, sQK, sQK);
    // 6) out = O @ wp + bp + x (residual)
    gemm64<0,1,1><<<dim3(8, 256, 1), 256>>>(o, wp, bp, x, out, 16384, 512, 512, 1.f, 0, 0, 0);
}

// round 3
// speedup vs baseline: 2.5338x; 2.5338x over previous
#include <cuda_runtime.h>
#include <math.h>
#include <stdint.h>

// Shapes: B=16, N=1024 (32x32), C=512, GROUPS=32
__device__ float g_xn[16u*1024u*512u];
__device__ float g_q [16u*1024u*512u];
__device__ float g_k [16u*1024u*512u];
__device__ float g_v [16u*1024u*512u];
__device__ float g_o [16u*1024u*512u];
__device__ float g_s [16u*1024u*1024u];

__device__ __forceinline__ uint32_t cvt_tf32(float f) {
    uint32_t o; asm("cvt.rna.tf32.f32 %0, %1;" : "=r"(o) : "f"(f)); return o;
}
__device__ __forceinline__ void mma_tf32(float* d, const uint32_t* a, const uint32_t* b) {
    asm volatile(
        "mma.sync.aligned.m16n8k8.row.col.f32.tf32.tf32.f32 "
        "{%0,%1,%2,%3}, {%4,%5,%6,%7}, {%8,%9}, {%0,%1,%2,%3};"
        : "+f"(d[0]), "+f"(d[1]), "+f"(d[2]), "+f"(d[3])
        : "r"(a[0]), "r"(a[1]), "r"(a[2]), "r"(a[3]), "r"(b[0]), "r"(b[1]));
}

// ---------------- tf32 mma.sync GEMM: 128x128 tile, BK=32 ----------------
// C[M,N] = alpha * A[M,K] @ op(B) (+bias) (+res), batched via blockIdx.z.
// TRANSB=1: B is [N,K] row-major (NT / B^T). TRANSB=0: B is [K,N] row-major (NN).
// 256 threads = 8 warps in 2(m) x 4(n); warp tile 64x32; thread does 4x4 mma tiles.
#define KPAD 36
template<int TRANSB, int HAS_BIAS, int HAS_RES>
__global__ void __launch_bounds__(256) mma_gemm(
    const float* __restrict__ A, const float* __restrict__ B,
    const float* __restrict__ bias, const float* __restrict__ res,
    float* __restrict__ C, int K, int lda, int ldb, int ldc, float alpha,
    size_t sA, size_t sB, size_t sC)
{
    __shared__ uint32_t As[128 * KPAD];   // [m][k] padded
    __shared__ uint32_t Bs[128 * KPAD];   // [n][k] padded

    const int tid  = threadIdx.x;
    const int wid  = tid >> 5;
    const int lane = tid & 31;
    const int g = lane >> 2;      // fragment row-group / n index
    const int c = lane & 3;       // fragment k index
    const int warp_m = wid >> 2;  // 0..1  (64 rows)
    const int warp_n = wid & 3;   // 0..3  (32 cols)
    const int rowBase = blockIdx.y * 128;
    const int colBase = blockIdx.x * 128;
    A += (size_t)blockIdx.z * sA;
    B += (size_t)blockIdx.z * sB;
    C += (size_t)blockIdx.z * sC;
    if (HAS_RES) res += (size_t)blockIdx.z * sC;

    float acc[4][4][4] = {};   // [mtile][ntile][4]

    // prefetch registers
    float4 pa[4];
    float4 pbt[4];     // TRANSB path
    float  pbn[16];    // NN path (transpose load)

    const int arow = tid >> 3, aseg = tid & 7;   // A loader: 32 rows/pass, 8 f4/row
    const int bk0  = tid >> 7, bn = tid & 127;   // NN B loader: column of B per thread

    auto ldg_stage = [&](int s) {
        const int k0 = s << 5;
        #pragma unroll
        for (int p = 0; p < 4; p++) {
            int r = arow + p * 32;
            pa[p] = *(const float4*)(A + (size_t)(rowBase + r) * lda + k0 + aseg * 4);
        }
        if (TRANSB) {
            #pragma unroll
            for (int p = 0; p < 4; p++) {
                int r = arow + p * 32;
                pbt[p] = *(const float4*)(B + (size_t)(colBase + r) * ldb + k0 + aseg * 4);
            }
        } else {
            #pragma unroll
            for (int p = 0; p < 16; p++) {
                int k = bk0 + 2 * p;
                pbn[p] = B[(size_t)(k0 + k) * ldb + colBase + bn];
            }
        }
    };
    auto sts_stage = [&]() {
        #pragma unroll
        for (int p = 0; p < 4; p++) {
            int r = arow + p * 32;
            uint32_t* d = &As[r * KPAD + aseg * 4];
            d[0] = cvt_tf32(pa[p].x); d[1] = cvt_tf32(pa[p].y);
            d[2] = cvt_tf32(pa[p].z); d[3] = cvt_tf32(pa[p].w);
        }
        if (TRANSB) {
            #pragma unroll
            for (int p = 0; p < 4; p++) {
                int r = arow + p * 32;
                uint32_t* d = &Bs[r * KPAD + aseg * 4];
                d[0] = cvt_tf32(pbt[p].x); d[1] = cvt_tf32(pbt[p].y);
                d[2] = cvt_tf32(pbt[p].z); d[3] = cvt_tf32(pbt[p].w);
            }
        } else {
            #pragma unroll
            for (int p = 0; p < 16; p++) {
                int k = bk0 + 2 * p;
                Bs[bn * KPAD + k] = cvt_tf32(pbn[p]);
            }
        }
    };

    const int nStages = K >> 5;
    ldg_stage(0);
    sts_stage();
    __syncthreads();

    for (int s = 0; s < nStages; s++) {
        if (s + 1 < nStages) ldg_stage(s + 1);
        #pragma unroll
        for (int ks = 0; ks < 4; ks++) {
            const int kk = ks * 8 + c;
            uint32_t af[4][4], bf[4][2];
            #pragma unroll
            for (int mt = 0; mt < 4; mt++) {
                const int m = warp_m * 64 + mt * 16 + g;
                af[mt][0] = As[m * KPAD + kk];
                af[mt][1] = As[(m + 8) * KPAD + kk];
                af[mt][2] = As[m * KPAD + kk + 4];
                af[mt][3] = As[(m + 8) * KPAD + kk + 4];
            }
            #pragma unroll
            for (int nt = 0; nt < 4; nt++) {
                const int n = warp_n * 32 + nt * 8 + g;
                bf[nt][0] = Bs[n * KPAD + kk];
                bf[nt][1] = Bs[n * KPAD + kk + 4];
            }
            #pragma unroll
            for (int mt = 0; mt < 4; mt++)
                #pragma unroll
                for (int nt = 0; nt < 4; nt++)
                    mma_tf32(acc[mt][nt], af[mt], bf[nt]);
        }
        __syncthreads();
        if (s + 1 < nStages) {
            sts_stage();
            __syncthreads();
        }
    }

    // Epilogue: thread owns rows (g, g+8) per mtile, col pairs 2c per ntile.
    #pragma unroll
    for (int mt = 0; mt < 4; mt++) {
        const int row0 = rowBase + warp_m * 64 + mt * 16 + g;
        #pragma unroll
        for (int nt = 0; nt < 4; nt++) {
            const int col = colBase + warp_n * 32 + nt * 8 + 2 * c;
            float2 v0, v1;
            v0.x = acc[mt][nt][0] * alpha; v0.y = acc[mt][nt][1] * alpha;
            v1.x = acc[mt][nt][2] * alpha; v1.y = acc[mt][nt][3] * alpha;
            if (HAS_BIAS) {
                float b0 = bias[col], b1 = bias[col + 1];
                v0.x += b0; v0.y += b1; v1.x += b0; v1.y += b1;
            }
            if (HAS_RES) {
                float2 r0 = *(const float2*)(res + (size_t)row0 * ldc + col);
                float2 r1 = *(const float2*)(res + (size_t)(row0 + 8) * ldc + col);
                v0.x += r0.x; v0.y += r0.y; v1.x += r1.x; v1.y += r1.y;
            }
            *(float2*)(C + (size_t)row0 * ldc + col) = v0;
            *(float2*)(C + (size_t)(row0 + 8) * ldc + col) = v1;
        }
    }
}

// ---------------- GroupNorm ----------------
__global__ void groupnorm_kernel(const float* __restrict__ x,
                                 const float* __restrict__ gamma,
                                 const float* __restrict__ beta,
                                 float* __restrict__ out) {
    const int b = blockIdx.x >> 5;
    const int g = blockIdx.x & 31;
    const float* xb = x + (size_t)b * 1024 * 512 + g * 16;
    float s1 = 0.f, s2 = 0.f;
    for (int i = threadIdx.x; i < 16384; i += 256) {
        int n = i >> 4, c = i & 15;
        float v = xb[(size_t)n * 512 + c];
        s1 += v; s2 += v * v;
    }
    __shared__ float r1[256], r2[256];
    r1[threadIdx.x] = s1; r2[threadIdx.x] = s2;
    __syncthreads();
    for (int off = 128; off > 0; off >>= 1) {
        if (threadIdx.x < off) {
            r1[threadIdx.x] += r1[threadIdx.x + off];
            r2[threadIdx.x] += r2[threadIdx.x + off];
        }
        __syncthreads();
    }
    const float mean = r1[0] * (1.f / 16384.f);
    const float var  = r2[0] * (1.f / 16384.f) - mean * mean;
    const float inv  = rsqrtf(var + 1e-3f);
    float* ob = out + (size_t)b * 1024 * 512 + g * 16;
    for (int i = threadIdx.x; i < 16384; i += 256) {
        int n = i >> 4, c = i & 15;
        int ch = g * 16 + c;
        float v = xb[(size_t)n * 512 + c];
        ob[(size_t)n * 512 + c] = (v - mean) * inv * gamma[ch] + beta[ch];
    }
}

// ---------------- Row softmax (1024) ----------------
__global__ void softmax1024(float* __restrict__ S) {
    float* p = S + (size_t)blockIdx.x * 1024;
    const int t = threadIdx.x;
    float4 x4 = ((float4*)p)[t];
    float m = fmaxf(fmaxf(x4.x, x4.y), fmaxf(x4.z, x4.w));
    __shared__ float red[256];
    red[t] = m;
    __syncthreads();
    for (int off = 128; off > 0; off >>= 1) {
        if (t < off) red[t] = fmaxf(red[t], red[t + off]);
        __syncthreads();
    }
    m = red[0];
    __syncthreads();
    x4.x = expf(x4.x - m); x4.y = expf(x4.y - m);
    x4.z = expf(x4.z - m); x4.w = expf(x4.w - m);
    red[t] = x4.x + x4.y + x4.z + x4.w;
    __syncthreads();
    for (int off = 128; off > 0; off >>= 1) {
        if (t < off) red[t] += red[t + off];
        __syncthreads();
    }
    const float inv = 1.f / red[0];
    x4.x *= inv; x4.y *= inv; x4.z *= inv; x4.w *= inv;
    ((float4*)p)[t] = x4;
}

extern "C" void kernel_launch(void* const* d_in, const int* in_sizes, int n_in,
                              void* d_out, int out_size) {
    const float* x     = (const float*)d_in[0];
    const float* gamma = (const float*)d_in[1];
    const float* beta  = (const float*)d_in[2];
    const float* wq    = (const float*)d_in[3];
    const float* bq    = (const float*)d_in[4];
    const float* wk    = (const float*)d_in[5];
    const float* bk    = (const float*)d_in[6];
    const float* wv    = (const float*)d_in[7];
    const float* bv    = (const float*)d_in[8];
    const float* wp    = (const float*)d_in[9];
    const float* bp    = (const float*)d_in[10];
    float* out = (float*)d_out;

    float *xn, *q, *k, *v, *o, *s;
    cudaGetSymbolAddress((void**)&xn, g_xn);
    cudaGetSymbolAddress((void**)&q,  g_q);
    cudaGetSymbolAddress((void**)&k,  g_k);
    cudaGetSymbolAddress((void**)&v,  g_v);
    cudaGetSymbolAddress((void**)&o,  g_o);
    cudaGetSymbolAddress((void**)&s,  g_s);

    const float scale = 0.044194173824159216f;  // 512^-0.5
    const size_t sQK = 1024u * 512u;
    const size_t sS  = 1024u * 1024u;

    // 1) GroupNorm
    groupnorm_kernel<<<512, 256>>>(x, gamma, beta, xn);
    // 2) Q, K, V projections: [16384,512] @ [512,512] + bias (NN)
    mma_gemm<0,1,0><<<dim3(4, 128, 1), 256>>>(xn, wq, bq, nullptr, q, 512, 512, 512, 512, 1.f, 0, 0, 0);
    mma_gemm<0,1,0><<<dim3(4, 128, 1), 256>>>(xn, wk, bk, nullptr, k, 512, 512, 512, 512, 1.f, 0, 0, 0);
    mma_gemm<0,1,0><<<dim3(4, 128, 1), 256>>>(xn, wv, bv, nullptr, v, 512, 512, 512, 512, 1.f, 0, 0, 0);
    // 3) scores = scale * Q @ K^T (batched NT)
    mma_gemm<1,0,0><<<dim3(8, 8, 16), 256>>>(q, k, nullptr, nullptr, s, 512, 512, 512, 1024, scale, sQK, sQK, sS);
    // 4) softmax rows
    softmax1024<<<16384, 256>>>(s);
    // 5) O = P @ V (batched NN)
    mma_gemm<0,0,0><<<dim3(4, 8, 16), 256>>>(s, v, nullptr, nullptr, o, 1024, 1024, 512, 512, 1.f, sS, sQK, sQK);
    // 6) out = O @ wp + bp + x (NN + bias + residual)
    mma_gemm<0,1,1><<<dim3(4, 128, 1), 256>>>(o, wp, bp, x, out, 512, 512, 512, 512, 1.f, 0, 0, 0);
}

// round 4
// speedup vs baseline: 3.7921x; 1.4966x over previous
#include <cuda_runtime.h>
#include <math.h>
#include <stdint.h>

// Shapes: B=16, N=1024 (32x32), C=512, GROUPS=32
__device__ float g_xn[16u*1024u*512u];
__device__ float g_q [16u*1024u*512u];
__device__ float g_k [16u*1024u*512u];
__device__ float g_v [16u*1024u*512u];
__device__ float g_o [16u*1024u*512u];
__device__ float g_s [16u*1024u*1024u];

__device__ __forceinline__ void mma_tf32(float* d, const uint32_t* a, const uint32_t* b) {
    asm volatile(
        "mma.sync.aligned.m16n8k8.row.col.f32.tf32.tf32.f32 "
        "{%0,%1,%2,%3}, {%4,%5,%6,%7}, {%8,%9}, {%0,%1,%2,%3};"
        : "+f"(d[0]), "+f"(d[1]), "+f"(d[2]), "+f"(d[3])
        : "r"(a[0]), "r"(a[1]), "r"(a[2]), "r"(a[3]), "r"(b[0]), "r"(b[1]));
}
__device__ __forceinline__ void cp16(uint32_t dst, const void* src) {
    asm volatile("cp.async.cg.shared.global [%0], [%1], 16;" :: "r"(dst), "l"(src));
}
__device__ __forceinline__ void cp_commit() {
    asm volatile("cp.async.commit_group;" ::: "memory");
}
template<int N> __device__ __forceinline__ void cp_wait() {
    asm volatile("cp.async.wait_group %0;" :: "n"(N) : "memory");
}

// ---------------- tf32 mma.sync GEMM, cp.async 3-stage pipeline ----------------
// 128x128 tile, BK=32, 256 threads (8 warps 2x4, warp tile 64x32).
// TRANSB=1: B is [N,K] row-major (NT). TRANSB=0: B is [K,N] row-major (NN).
// Smem: As [3][128][36] w; Bs TRANSB [3][128][36] w, NN [3][32][136] w.
#define KPAD 36
#define NPAD 136
#define A_STG (128 * KPAD)
template<int TRANSB, int HAS_BIAS, int HAS_RES>
__global__ void __launch_bounds__(256, 2) mma_gemm(
    const float* __restrict__ A, const float* __restrict__ B,
    const float* __restrict__ bias, const float* __restrict__ res,
    float* __restrict__ C, int K, int lda, int ldb, int ldc, float alpha,
    size_t sA, size_t sB, size_t sC)
{
    extern __shared__ __align__(16) uint32_t smem[];
    const int B_STG = TRANSB ? (128 * KPAD) : (32 * NPAD);
    uint32_t* Asm = smem;                 // 3 stages
    uint32_t* Bsm = smem + 3 * A_STG;     // 3 stages

    const int tid  = threadIdx.x;
    const int wid  = tid >> 5;
    const int lane = tid & 31;
    const int g = lane >> 2;      // 0..7
    const int c = lane & 3;       // 0..3
    const int warp_m = wid >> 2;  // 0..1
    const int warp_n = wid & 3;   // 0..3
    const int rowBase = blockIdx.y * 128;
    const int colBase = blockIdx.x * 128;
    A += (size_t)blockIdx.z * sA;
    B += (size_t)blockIdx.z * sB;
    C += (size_t)blockIdx.z * sC;
    if (HAS_RES) res += (size_t)blockIdx.z * sC;

    uint32_t sAbase, sBbase;
    {
        uint64_t t = __cvta_generic_to_shared(Asm);
        sAbase = (uint32_t)t;
        t = __cvta_generic_to_shared(Bsm);
        sBbase = (uint32_t)t;
    }

    const int arow = tid >> 3, aseg = tid & 7;   // A/TRANSB-B loader
    const int bk = tid >> 3, bseg = tid & 7;     // NN-B loader

    auto cp_stage = [&](int s) {
        const int k0 = s << 5;
        const uint32_t abuf = sAbase + (uint32_t)((s % 3) * A_STG) * 4u;
        #pragma unroll
        for (int p = 0; p < 4; p++) {
            int r = arow + p * 32;
            cp16(abuf + (uint32_t)(r * KPAD + aseg * 4) * 4u,
                 A + (size_t)(rowBase + r) * lda + k0 + aseg * 4);
        }
        const uint32_t bbuf = sBbase + (uint32_t)((s % 3) * B_STG) * 4u;
        if (TRANSB) {
            #pragma unroll
            for (int p = 0; p < 4; p++) {
                int r = arow + p * 32;
                cp16(bbuf + (uint32_t)(r * KPAD + aseg * 4) * 4u,
                     B + (size_t)(colBase + r) * ldb + k0 + aseg * 4);
            }
        } else {
            #pragma unroll
            for (int p = 0; p < 4; p++) {
                int ci = bseg + p * 8;
                cp16(bbuf + (uint32_t)(bk * NPAD + ci * 4) * 4u,
                     B + (size_t)(k0 + bk) * ldb + colBase + ci * 4);
            }
        }
    };

    float acc[4][4][4] = {};

    const int nStages = K >> 5;
    cp_stage(0); cp_commit();
    cp_stage(1); cp_commit();

    for (int s = 0; s < nStages; s++) {
        if (s + 1 < nStages) cp_wait<1>(); else cp_wait<0>();
        __syncthreads();
        const uint32_t* Abuf = Asm + (s % 3) * A_STG;
        const uint32_t* Bbuf = Bsm + (s % 3) * B_STG;
        #pragma unroll
        for (int ks = 0; ks < 4; ks++) {
            const int kk = ks * 8 + c;
            uint32_t af[4][4], bf[4][2];
            #pragma unroll
            for (int mt = 0; mt < 4; mt++) {
                const int m = warp_m * 64 + mt * 16 + g;
                af[mt][0] = Abuf[m * KPAD + kk];
                af[mt][1] = Abuf[(m + 8) * KPAD + kk];
                af[mt][2] = Abuf[m * KPAD + kk + 4];
                af[mt][3] = Abuf[(m + 8) * KPAD + kk + 4];
            }
            #pragma unroll
            for (int nt = 0; nt < 4; nt++) {
                const int n = warp_n * 32 + nt * 8 + g;
                if (TRANSB) {
                    bf[nt][0] = Bbuf[n * KPAD + kk];
                    bf[nt][1] = Bbuf[n * KPAD + kk + 4];
                } else {
                    bf[nt][0] = Bbuf[kk * NPAD + n];
                    bf[nt][1] = Bbuf[(kk + 4) * NPAD + n];
                }
            }
            #pragma unroll
            for (int mt = 0; mt < 4; mt++)
                #pragma unroll
                for (int nt = 0; nt < 4; nt++)
                    mma_tf32(acc[mt][nt], af[mt], bf[nt]);
        }
        __syncthreads();
        if (s + 2 < nStages) { cp_stage(s + 2); cp_commit(); }
    }

    // Epilogue
    #pragma unroll
    for (int mt = 0; mt < 4; mt++) {
        const int row0 = rowBase + warp_m * 64 + mt * 16 + g;
        #pragma unroll
        for (int nt = 0; nt < 4; nt++) {
            const int col = colBase + warp_n * 32 + nt * 8 + 2 * c;
            float2 v0, v1;
            v0.x = acc[mt][nt][0] * alpha; v0.y = acc[mt][nt][1] * alpha;
            v1.x = acc[mt][nt][2] * alpha; v1.y = acc[mt][nt][3] * alpha;
            if (HAS_BIAS) {
                float b0 = bias[col], b1 = bias[col + 1];
                v0.x += b0; v0.y += b1; v1.x += b0; v1.y += b1;
            }
            if (HAS_RES) {
                float2 r0 = *(const float2*)(res + (size_t)row0 * ldc + col);
                float2 r1 = *(const float2*)(res + (size_t)(row0 + 8) * ldc + col);
                v0.x += r0.x; v0.y += r0.y; v1.x += r1.x; v1.y += r1.y;
            }
            *(float2*)(C + (size_t)row0 * ldc + col) = v0;
            *(float2*)(C + (size_t)(row0 + 8) * ldc + col) = v1;
        }
    }
}

// ---------------- GroupNorm ----------------
__global__ void groupnorm_kernel(const float* __restrict__ x,
                                 const float* __restrict__ gamma,
                                 const float* __restrict__ beta,
                                 float* __restrict__ out) {
    const int b = blockIdx.x >> 5;
    const int g = blockIdx.x & 31;
    const float* xb = x + (size_t)b * 1024 * 512 + g * 16;
    float s1 = 0.f, s2 = 0.f;
    for (int i = threadIdx.x; i < 16384; i += 256) {
        int n = i >> 4, c = i & 15;
        float v = xb[(size_t)n * 512 + c];
        s1 += v; s2 += v * v;
    }
    __shared__ float r1[256], r2[256];
    r1[threadIdx.x] = s1; r2[threadIdx.x] = s2;
    __syncthreads();
    for (int off = 128; off > 0; off >>= 1) {
        if (threadIdx.x < off) {
            r1[threadIdx.x] += r1[threadIdx.x + off];
            r2[threadIdx.x] += r2[threadIdx.x + off];
        }
        __syncthreads();
    }
    const float mean = r1[0] * (1.f / 16384.f);
    const float var  = r2[0] * (1.f / 16384.f) - mean * mean;
    const float inv  = rsqrtf(var + 1e-3f);
    float* ob = out + (size_t)b * 1024 * 512 + g * 16;
    for (int i = threadIdx.x; i < 16384; i += 256) {
        int n = i >> 4, c = i & 15;
        int ch = g * 16 + c;
        float v = xb[(size_t)n * 512 + c];
        ob[(size_t)n * 512 + c] = (v - mean) * inv * gamma[ch] + beta[ch];
    }
}

// ---------------- Row softmax (1024) ----------------
__global__ void softmax1024(float* __restrict__ S) {
    float* p = S + (size_t)blockIdx.x * 1024;
    const int t = threadIdx.x;
    const int w = t >> 5, l = t & 31;
    float4 x4 = ((float4*)p)[t];
    float m = fmaxf(fmaxf(x4.x, x4.y), fmaxf(x4.z, x4.w));
    __shared__ float red[8];
    #pragma unroll
    for (int off = 16; off > 0; off >>= 1)
        m = fmaxf(m, __shfl_xor_sync(0xffffffffu, m, off));
    if (l == 0) red[w] = m;
    __syncthreads();
    m = red[0];
    #pragma unroll
    for (int i = 1; i < 8; i++) m = fmaxf(m, red[i]);
    x4.x = __expf(x4.x - m); x4.y = __expf(x4.y - m);
    x4.z = __expf(x4.z - m); x4.w = __expf(x4.w - m);
    float sum = x4.x + x4.y + x4.z + x4.w;
    #pragma unroll
    for (int off = 16; off > 0; off >>= 1)
        sum += __shfl_xor_sync(0xffffffffu, sum, off);
    __syncthreads();
    if (l == 0) red[w] = sum;
    __syncthreads();
    sum = 0.f;
    #pragma unroll
    for (int i = 0; i < 8; i++) sum += red[i];
    const float inv = 1.f / sum;
    x4.x *= inv; x4.y *= inv; x4.z *= inv; x4.w *= inv;
    ((float4*)p)[t] = x4;
}

extern "C" void kernel_launch(void* const* d_in, const int* in_sizes, int n_in,
                              void* d_out, int out_size) {
    const float* x     = (const float*)d_in[0];
    const float* gamma = (const float*)d_in[1];
    const float* beta  = (const float*)d_in[2];
    const float* wq    = (const float*)d_in[3];
    const float* bq    = (const float*)d_in[4];
    const float* wk    = (const float*)d_in[5];
    const float* bk    = (const float*)d_in[6];
    const float* wv    = (const float*)d_in[7];
    const float* bv    = (const float*)d_in[8];
    const float* wp    = (const float*)d_in[9];
    const float* bp    = (const float*)d_in[10];
    float* out = (float*)d_out;

    float *xn, *q, *k, *v, *o, *s;
    cudaGetSymbolAddress((void**)&xn, g_xn);
    cudaGetSymbolAddress((void**)&q,  g_q);
    cudaGetSymbolAddress((void**)&k,  g_k);
    cudaGetSymbolAddress((void**)&v,  g_v);
    cudaGetSymbolAddress((void**)&o,  g_o);
    cudaGetSymbolAddress((void**)&s,  g_s);

    const int SMEM_NN = (3 * 128 * KPAD + 3 * 32 * NPAD) * 4;   // 107520
    const int SMEM_NT = (3 * 128 * KPAD + 3 * 128 * KPAD) * 4;  // 110592
    cudaFuncSetAttribute(mma_gemm<0,1,0>, cudaFuncAttributeMaxDynamicSharedMemorySize, SMEM_NN);
    cudaFuncSetAttribute(mma_gemm<1,0,0>, cudaFuncAttributeMaxDynamicSharedMemorySize, SMEM_NT);
    cudaFuncSetAttribute(mma_gemm<0,0,0>, cudaFuncAttributeMaxDynamicSharedMemorySize, SMEM_NN);
    cudaFuncSetAttribute(mma_gemm<0,1,1>, cudaFuncAttributeMaxDynamicSharedMemorySize, SMEM_NN);

    const float scale = 0.044194173824159216f;  // 512^-0.5
    const size_t sQK = 1024u * 512u;
    const size_t sS  = 1024u * 1024u;

    // 1) GroupNorm
    groupnorm_kernel<<<512, 256>>>(x, gamma, beta, xn);
    // 2) Q, K, V projections (NN + bias)
    mma_gemm<0,1,0><<<dim3(4, 128, 1), 256, SMEM_NN>>>(xn, wq, bq, nullptr, q, 512, 512, 512, 512, 1.f, 0, 0, 0);
    mma_gemm<0,1,0><<<dim3(4, 128, 1), 256, SMEM_NN>>>(xn, wk, bk, nullptr, k, 512, 512, 512, 512, 1.f, 0, 0, 0);
    mma_gemm<0,1,0><<<dim3(4, 128, 1), 256, SMEM_NN>>>(xn, wv, bv, nullptr, v, 512, 512, 512, 512, 1.f, 0, 0, 0);
    // 3) scores = scale * Q @ K^T (batched NT)
    mma_gemm<1,0,0><<<dim3(8, 8, 16), 256, SMEM_NT>>>(q, k, nullptr, nullptr, s, 512, 512, 512, 1024, scale, sQK, sQK, sS);
    // 4) softmax rows
    softmax1024<<<16384, 256>>>(s);
    // 5) O = P @ V (batched NN)
    mma_gemm<0,0,0><<<dim3(4, 8, 16), 256, SMEM_NN>>>(s, v, nullptr, nullptr, o, 1024, 1024, 512, 512, 1.f, sS, sQK, sQK);
    // 6) out = O @ wp + bp + x (NN + bias + residual)
    mma_gemm<0,1,1><<<dim3(4, 128, 1), 256, SMEM_NN>>>(o, wp, bp, x, out, 512, 512, 512, 512, 1.f, 0, 0, 0);
}

// round 5
// speedup vs baseline: 6.1423x; 1.6198x over previous
#include <cuda_runtime.h>
#include <cuda_fp16.h>
#include <math.h>
#include <stdint.h>

// Shapes: B=16, N=1024 (32x32), C=512, GROUPS=32
__device__ __half g_xn [16384u*512u];
__device__ __half g_w  [4u*512u*512u];     // wq|wk|wv|wp fp16
__device__ float  g_b  [3u*512u];          // bq|bk|bv
__device__ __half g_qkv[3u*16384u*512u];   // q|k|v
__device__ float  g_s  [16u*1024u*1024u];  // scores fp32
__device__ __half g_p  [16u*1024u*1024u];  // softmax(P) fp16
__device__ __half g_o  [16384u*512u];      // attention out fp16

__device__ __forceinline__ void mma_f16(float* d, const uint32_t* a, const uint32_t* b) {
    asm volatile(
        "mma.sync.aligned.m16n8k16.row.col.f32.f16.f16.f32 "
        "{%0,%1,%2,%3}, {%4,%5,%6,%7}, {%8,%9}, {%0,%1,%2,%3};"
        : "+f"(d[0]), "+f"(d[1]), "+f"(d[2]), "+f"(d[3])
        : "r"(a[0]), "r"(a[1]), "r"(a[2]), "r"(a[3]), "r"(b[0]), "r"(b[1]));
}
__device__ __forceinline__ void cp16(uint32_t dst, const void* src) {
    asm volatile("cp.async.cg.shared.global [%0], [%1], 16;" :: "r"(dst), "l"(src));
}
__device__ __forceinline__ void cp_commit() {
    asm volatile("cp.async.commit_group;" ::: "memory");
}
template<int N> __device__ __forceinline__ void cp_wait() {
    asm volatile("cp.async.wait_group %0;" :: "n"(N) : "memory");
}
__device__ __forceinline__ void ldm_x4(uint32_t* r, uint32_t a) {
    asm volatile("ldmatrix.sync.aligned.m8n8.x4.shared.b16 {%0,%1,%2,%3}, [%4];"
                 : "=r"(r[0]), "=r"(r[1]), "=r"(r[2]), "=r"(r[3]) : "r"(a));
}
__device__ __forceinline__ void ldm_x4_t(uint32_t* r, uint32_t a) {
    asm volatile("ldmatrix.sync.aligned.m8n8.x4.trans.shared.b16 {%0,%1,%2,%3}, [%4];"
                 : "=r"(r[0]), "=r"(r[1]), "=r"(r[2]), "=r"(r[3]) : "r"(a));
}

// ---------------- fp16 mma.sync GEMM: 128x128 tile, BK=32, 4-stage cp.async ----------------
// TRANSB=1: B is [N,K] row-major (NT). TRANSB=0: B is [K,N] row-major (NN).
// 256 threads = 8 warps (2m x 4n), warp tile 64x32, m16n8k16.
#define APITCH 40           // halves per A/NT-B smem row (80B, conflict-free ldmatrix)
#define BPITCH 136          // halves per NN-B smem row (272B, conflict-free trans ldmatrix)
#define A_STG (128 * APITCH)
#define NSTG 4
template<int TRANSB, int HAS_BIAS, int HAS_RES, int OUT_HALF>
__global__ void __launch_bounds__(256, 2) mma_gemm(
    const __half* __restrict__ A, const __half* __restrict__ B,
    const float* __restrict__ bias, const float* __restrict__ res,
    void* __restrict__ Cv, int K, int lda, int ldb, int ldc, float alpha,
    size_t sA, size_t sB, size_t sC, int biasStride)
{
    extern __shared__ __align__(16) __half smem[];
    const int B_STG = TRANSB ? A_STG : (32 * BPITCH);
    __half* Asm = smem;
    __half* Bsm = smem + NSTG * A_STG;

    const int tid  = threadIdx.x;
    const int wid  = tid >> 5;
    const int lane = tid & 31;
    const int g = lane >> 2, c = lane & 3;
    const int warp_m = wid >> 2;  // 0..1
    const int warp_n = wid & 3;   // 0..3
    const int rowBase = blockIdx.y * 128;
    const int colBase = blockIdx.x * 128;
    A += (size_t)blockIdx.z * sA;
    B += (size_t)blockIdx.z * sB;
    if (HAS_BIAS) bias += (size_t)blockIdx.z * biasStride;
    __half* Ch = (__half*)Cv + (size_t)blockIdx.z * sC;
    float*  Cf = (float*)Cv  + (size_t)blockIdx.z * sC;

    const uint32_t sAbase = (uint32_t)__cvta_generic_to_shared(Asm);
    const uint32_t sBbase = (uint32_t)__cvta_generic_to_shared(Bsm);

    auto cp_stage = [&](int s) {
        const int k0 = s << 5;
        const uint32_t ab = sAbase + (uint32_t)((s & 3) * A_STG) * 2u;
        #pragma unroll
        for (int i = 0; i < 2; i++) {
            int idx = tid * 2 + i, r = idx >> 2, seg = idx & 3;
            cp16(ab + (uint32_t)(r * APITCH + seg * 8) * 2u,
                 A + (size_t)(rowBase + r) * lda + k0 + seg * 8);
        }
        const uint32_t bb = sBbase + (uint32_t)((s & 3) * B_STG) * 2u;
        if (TRANSB) {
            #pragma unroll
            for (int i = 0; i < 2; i++) {
                int idx = tid * 2 + i, r = idx >> 2, seg = idx & 3;
                cp16(bb + (uint32_t)(r * APITCH + seg * 8) * 2u,
                     B + (size_t)(colBase + r) * ldb + k0 + seg * 8);
            }
        } else {
            #pragma unroll
            for (int i = 0; i < 2; i++) {
                int idx = tid * 2 + i, kr = idx >> 4, seg = idx & 15;
                cp16(bb + (uint32_t)(kr * BPITCH + seg * 8) * 2u,
                     B + (size_t)(k0 + kr) * ldb + colBase + seg * 8);
            }
        }
    };

    float acc[4][4][4] = {};
    const int nStages = K >> 5;
    cp_stage(0); cp_commit();
    cp_stage(1); cp_commit();
    cp_stage(2); cp_commit();

    for (int s = 0; s < nStages; s++) {
        cp_wait<2>();
        __syncthreads();
        if (s + 3 < nStages) cp_stage(s + 3);
        cp_commit();   // always commit (possibly empty) to keep group accounting exact
        const uint32_t sAb = sAbase + (uint32_t)((s & 3) * A_STG) * 2u;
        const uint32_t sBb = sBbase + (uint32_t)((s & 3) * B_STG) * 2u;
        #pragma unroll
        for (int ks = 0; ks < 2; ks++) {
            uint32_t af[4][4];
            #pragma unroll
            for (int mt = 0; mt < 4; mt++) {
                const int m0 = warp_m * 64 + mt * 16;
                uint32_t ad = sAb + (uint32_t)((m0 + (lane & 15)) * APITCH
                                   + ks * 16 + ((lane >> 4) & 1) * 8) * 2u;
                ldm_x4(af[mt], ad);
            }
            uint32_t bf[4][2];
            #pragma unroll
            for (int ntp = 0; ntp < 2; ntp++) {
                const int n0 = warp_n * 32 + ntp * 16;
                uint32_t r[4];
                if (TRANSB) {
                    uint32_t bd = sBb + (uint32_t)((n0 + (lane & 15)) * APITCH
                                       + ks * 16 + ((lane >> 4) & 1) * 8) * 2u;
                    ldm_x4(r, bd);
                    bf[2*ntp][0] = r[0]; bf[2*ntp][1] = r[2];
                    bf[2*ntp+1][0] = r[1]; bf[2*ntp+1][1] = r[3];
                } else {
                    uint32_t bd = sBb + (uint32_t)((ks * 16 + (lane & 15)) * BPITCH
                                       + n0 + ((lane >> 4) & 1) * 8) * 2u;
                    ldm_x4_t(r, bd);
                    bf[2*ntp][0] = r[0]; bf[2*ntp][1] = r[1];
                    bf[2*ntp+1][0] = r[2]; bf[2*ntp+1][1] = r[3];
                }
            }
            #pragma unroll
            for (int mt = 0; mt < 4; mt++)
                #pragma unroll
                for (int nt = 0; nt < 4; nt++)
                    mma_f16(acc[mt][nt], af[mt], bf[nt]);
        }
    }

    // Epilogue
    #pragma unroll
    for (int mt = 0; mt < 4; mt++) {
        const int row0 = rowBase + warp_m * 64 + mt * 16 + g;
        #pragma unroll
        for (int nt = 0; nt < 4; nt++) {
            const int col = colBase + warp_n * 32 + nt * 8 + 2 * c;
            float v0 = acc[mt][nt][0] * alpha, v1 = acc[mt][nt][1] * alpha;
            float v2 = acc[mt][nt][2] * alpha, v3 = acc[mt][nt][3] * alpha;
            if (HAS_BIAS) {
                float b0 = bias[col], b1 = bias[col + 1];
                v0 += b0; v1 += b1; v2 += b0; v3 += b1;
            }
            if (HAS_RES) {
                float2 r0 = *(const float2*)(res + (size_t)row0 * ldc + col);
                float2 r1 = *(const float2*)(res + (size_t)(row0 + 8) * ldc + col);
                v0 += r0.x; v1 += r0.y; v2 += r1.x; v3 += r1.y;
            }
            if (OUT_HALF) {
                *(__half2*)(Ch + (size_t)row0 * ldc + col)       = __floats2half2_rn(v0, v1);
                *(__half2*)(Ch + (size_t)(row0 + 8) * ldc + col) = __floats2half2_rn(v2, v3);
            } else {
                *(float2*)(Cf + (size_t)row0 * ldc + col)       = make_float2(v0, v1);
                *(float2*)(Cf + (size_t)(row0 + 8) * ldc + col) = make_float2(v2, v3);
            }
        }
    }
}

// ---------------- weight/bias convert (fp32 -> fp16, concat) ----------------
__global__ void cvt_weights(const float* __restrict__ wq, const float* __restrict__ wk,
                            const float* __restrict__ wv, const float* __restrict__ wp,
                            const float* __restrict__ bq, const float* __restrict__ bk,
                            const float* __restrict__ bv,
                            __half* __restrict__ W, float* __restrict__ Bc) {
    const int j = blockIdx.y;
    const float* src = (j == 0) ? wq : (j == 1) ? wk : (j == 2) ? wv : wp;
    const int i = (blockIdx.x * 256 + threadIdx.x) * 4;
    float4 v = *(const float4*)(src + i);
    __half2* dst = (__half2*)(W + (size_t)j * 262144 + i);
    dst[0] = __floats2half2_rn(v.x, v.y);
    dst[1] = __floats2half2_rn(v.z, v.w);
    if (j < 3 && i < 512) {
        const float* bs = (j == 0) ? bq : (j == 1) ? bk : bv;
        *(float4*)(Bc + j * 512 + i) = *(const float4*)(bs + i);
    }
}

// ---------------- GroupNorm (fp32 in, fp16 out) ----------------
__global__ void groupnorm_kernel(const float* __restrict__ x,
                                 const float* __restrict__ gamma,
                                 const float* __restrict__ beta,
                                 __half* __restrict__ out) {
    const int b = blockIdx.x >> 5;
    const int g = blockIdx.x & 31;
    const float* xb = x + (size_t)b * 1024 * 512 + g * 16;
    float s1 = 0.f, s2 = 0.f;
    for (int i = threadIdx.x; i < 16384; i += 256) {
        int n = i >> 4, c = i & 15;
        float v = xb[(size_t)n * 512 + c];
        s1 += v; s2 += v * v;
    }
    __shared__ float r1[256], r2[256];
    r1[threadIdx.x] = s1; r2[threadIdx.x] = s2;
    __syncthreads();
    for (int off = 128; off > 0; off >>= 1) {
        if (threadIdx.x < off) {
            r1[threadIdx.x] += r1[threadIdx.x + off];
            r2[threadIdx.x] += r2[threadIdx.x + off];
        }
        __syncthreads();
    }
    const float mean = r1[0] * (1.f / 16384.f);
    const float var  = r2[0] * (1.f / 16384.f) - mean * mean;
    const float inv  = rsqrtf(var + 1e-3f);
    __half* ob = out + (size_t)b * 1024 * 512 + g * 16;
    for (int i = threadIdx.x; i < 16384; i += 256) {
        int n = i >> 4, c = i & 15;
        int ch = g * 16 + c;
        float v = xb[(size_t)n * 512 + c];
        ob[(size_t)n * 512 + c] = __float2half((v - mean) * inv * gamma[ch] + beta[ch]);
    }
}

// ---------------- Row softmax 1024 (fp32 in, fp16 out) ----------------
__global__ void softmax1024(const float* __restrict__ S, __half* __restrict__ P) {
    const float* p = S + (size_t)blockIdx.x * 1024;
    __half* o = P + (size_t)blockIdx.x * 1024;
    const int t = threadIdx.x;
    const int w = t >> 5, l = t & 31;
    float4 x4 = ((const float4*)p)[t];
    float m = fmaxf(fmaxf(x4.x, x4.y), fmaxf(x4.z, x4.w));
    __shared__ float red[8];
    #pragma unroll
    for (int off = 16; off > 0; off >>= 1)
        m = fmaxf(m, __shfl_xor_sync(0xffffffffu, m, off));
    if (l == 0) red[w] = m;
    __syncthreads();
    m = red[0];
    #pragma unroll
    for (int i = 1; i < 8; i++) m = fmaxf(m, red[i]);
    x4.x = __expf(x4.x - m); x4.y = __expf(x4.y - m);
    x4.z = __expf(x4.z - m); x4.w = __expf(x4.w - m);
    float sum = x4.x + x4.y + x4.z + x4.w;
    #pragma unroll
    for (int off = 16; off > 0; off >>= 1)
        sum += __shfl_xor_sync(0xffffffffu, sum, off);
    __syncthreads();
    if (l == 0) red[w] = sum;
    __syncthreads();
    sum = 0.f;
    #pragma unroll
    for (int i = 0; i < 8; i++) sum += red[i];
    const float inv = 1.f / sum;
    ((__half2*)o)[2 * t]     = __floats2half2_rn(x4.x * inv, x4.y * inv);
    ((__half2*)o)[2 * t + 1] = __floats2half2_rn(x4.z * inv, x4.w * inv);
}

extern "C" void kernel_launch(void* const* d_in, const int* in_sizes, int n_in,
                              void* d_out, int out_size) {
    const float* x     = (const float*)d_in[0];
    const float* gamma = (const float*)d_in[1];
    const float* beta  = (const float*)d_in[2];
    const float* wq    = (const float*)d_in[3];
    const float* bq    = (const float*)d_in[4];
    const float* wk    = (const float*)d_in[5];
    const float* bk    = (const float*)d_in[6];
    const float* wv    = (const float*)d_in[7];
    const float* bv    = (const float*)d_in[8];
    const float* wp    = (const float*)d_in[9];
    const float* bp    = (const float*)d_in[10];
    float* out = (float*)d_out;

    __half *xn, *W, *qkv, *p, *o;
    float *Bc, *s;
    cudaGetSymbolAddress((void**)&xn,  g_xn);
    cudaGetSymbolAddress((void**)&W,   g_w);
    cudaGetSymbolAddress((void**)&Bc,  g_b);
    cudaGetSymbolAddress((void**)&qkv, g_qkv);
    cudaGetSymbolAddress((void**)&s,   g_s);
    cudaGetSymbolAddress((void**)&p,   g_p);
    cudaGetSymbolAddress((void**)&o,   g_o);

    const int SMEM_NT = NSTG * (A_STG + A_STG) * 2;            // 81920
    const int SMEM_NN = NSTG * (A_STG + 32 * BPITCH) * 2;      // 75776
    cudaFuncSetAttribute(mma_gemm<0,1,0,1>, cudaFuncAttributeMaxDynamicSharedMemorySize, SMEM_NN);
    cudaFuncSetAttribute(mma_gemm<1,0,0,0>, cudaFuncAttributeMaxDynamicSharedMemorySize, SMEM_NT);
    cudaFuncSetAttribute(mma_gemm<0,0,0,1>, cudaFuncAttributeMaxDynamicSharedMemorySize, SMEM_NN);
    cudaFuncSetAttribute(mma_gemm<0,1,1,0>, cudaFuncAttributeMaxDynamicSharedMemorySize, SMEM_NN);

    const float scale = 0.044194173824159216f;  // 512^-0.5
    const size_t sQK = 1024u * 512u;   // 524288
    const size_t sS  = 1024u * 1024u;  // 1048576
    const size_t kOff = 16u * sQK;     // 8388608
    const size_t vOff = 32u * sQK;     // 16777216

    // 0) convert weights/biases to fp16 scratch
    cvt_weights<<<dim3(256, 4), 256>>>(wq, wk, wv, wp, bq, bk, bv, W, Bc);
    // 1) GroupNorm -> fp16 xn
    groupnorm_kernel<<<512, 256>>>(x, gamma, beta, xn);
    // 2) fused Q|K|V projection: z selects weight/bias/output
    mma_gemm<0,1,0,1><<<dim3(4, 128, 3), 256, SMEM_NN>>>(
        xn, W, Bc, nullptr, qkv, 512, 512, 512, 512, 1.f,
        0, 262144, 16u * sQK, 512);
    // 3) scores = scale * Q @ K^T (batched NT, fp32 out)
    mma_gemm<1,0,0,0><<<dim3(8, 8, 16), 256, SMEM_NT>>>(
        qkv, qkv + kOff, nullptr, nullptr, s, 512, 512, 512, 1024, scale,
        sQK, sQK, sS, 0);
    // 4) softmax rows -> fp16 P
    softmax1024<<<16384, 256>>>(s, p);
    // 5) O = P @ V (batched NN, fp16 out)
    mma_gemm<0,0,0,1><<<dim3(4, 8, 16), 256, SMEM_NN>>>(
        p, qkv + vOff, nullptr, nullptr, o, 1024, 1024, 512, 512, 1.f,
        sS, sQK, sQK, 0);
    // 6) out = O @ wp + bp + x (NN + bias + residual, fp32 out)
    mma_gemm<0,1,1,0><<<dim3(4, 128, 1), 256, SMEM_NN>>>(
        o, W + 3u * 262144u, bp, x, out, 512, 512, 512, 512, 1.f,
        0, 0, 0, 0);
}

// round 6
// speedup vs baseline: 6.8158x; 1.1096x over previous
#include <cuda_runtime.h>
#include <cuda_fp16.h>
#include <math.h>
#include <stdint.h>

// Shapes: B=16, N=1024 (32x32), C=512, GROUPS=32
__device__ __half g_xn [16384u*512u];
__device__ __half g_w  [4u*512u*512u];     // wq|wk|wv|wp fp16
__device__ float  g_b  [3u*512u];          // bq|bk|bv
__device__ __half g_qkv[3u*16384u*512u];   // q|k|v
__device__ float  g_s  [16u*1024u*1024u];  // scores fp32
__device__ __half g_p  [16u*1024u*1024u];  // softmax(P) fp16
__device__ __half g_o  [16384u*512u];      // attention out fp16

__device__ __forceinline__ void mma_f16(float* d, const uint32_t* a, const uint32_t* b) {
    asm volatile(
        "mma.sync.aligned.m16n8k16.row.col.f32.f16.f16.f32 "
        "{%0,%1,%2,%3}, {%4,%5,%6,%7}, {%8,%9}, {%0,%1,%2,%3};"
        : "+f"(d[0]), "+f"(d[1]), "+f"(d[2]), "+f"(d[3])
        : "r"(a[0]), "r"(a[1]), "r"(a[2]), "r"(a[3]), "r"(b[0]), "r"(b[1]));
}
__device__ __forceinline__ void cp16(uint32_t dst, const void* src) {
    asm volatile("cp.async.cg.shared.global [%0], [%1], 16;" :: "r"(dst), "l"(src));
}
__device__ __forceinline__ void cp_commit() {
    asm volatile("cp.async.commit_group;" ::: "memory");
}
template<int N> __device__ __forceinline__ void cp_wait() {
    asm volatile("cp.async.wait_group %0;" :: "n"(N) : "memory");
}
__device__ __forceinline__ void ldm_x4(uint32_t* r, uint32_t a) {
    asm volatile("ldmatrix.sync.aligned.m8n8.x4.shared.b16 {%0,%1,%2,%3}, [%4];"
                 : "=r"(r[0]), "=r"(r[1]), "=r"(r[2]), "=r"(r[3]) : "r"(a));
}
__device__ __forceinline__ void ldm_x4_t(uint32_t* r, uint32_t a) {
    asm volatile("ldmatrix.sync.aligned.m8n8.x4.trans.shared.b16 {%0,%1,%2,%3}, [%4];"
                 : "=r"(r[0]), "=r"(r[1]), "=r"(r[2]), "=r"(r[3]) : "r"(a));
}

// ---------------- fp16 mma.sync GEMM: 128x128 tile, BK=64, 3-stage cp.async ----------------
// TRANSB=1: B is [N,K] row-major (NT). TRANSB=0: B is [K,N] row-major (NN).
// 256 threads = 8 warps (2m x 4n), warp tile 64x32, m16n8k16. 64 MMAs/warp per barrier.
#define APITCH 72           // halves per A/NT-B smem row (144B, conflict-free ldmatrix)
#define BPITCH 136          // halves per NN-B smem row (272B, conflict-free trans ldmatrix)
#define A_STG (128 * APITCH)
#define NSTG 3
template<int TRANSB, int HAS_BIAS, int HAS_RES, int OUT_HALF>
__global__ void __launch_bounds__(256, 2) mma_gemm(
    const __half* __restrict__ A, const __half* __restrict__ B,
    const float* __restrict__ bias, const float* __restrict__ res,
    void* __restrict__ Cv, int K, int lda, int ldb, int ldc, float alpha,
    size_t sA, size_t sB, size_t sC, int biasStride)
{
    extern __shared__ __align__(16) __half smem[];
    const int B_STG = TRANSB ? A_STG : (64 * BPITCH);
    __half* Asm = smem;
    __half* Bsm = smem + NSTG * A_STG;

    const int tid  = threadIdx.x;
    const int wid  = tid >> 5;
    const int lane = tid & 31;
    const int g = lane >> 2, c = lane & 3;
    const int warp_m = wid >> 2;  // 0..1
    const int warp_n = wid & 3;   // 0..3
    const int rowBase = blockIdx.y * 128;
    const int colBase = blockIdx.x * 128;
    A += (size_t)blockIdx.z * sA;
    B += (size_t)blockIdx.z * sB;
    if (HAS_BIAS) bias += (size_t)blockIdx.z * biasStride;
    __half* Ch = (__half*)Cv + (size_t)blockIdx.z * sC;
    float*  Cf = (float*)Cv  + (size_t)blockIdx.z * sC;

    const uint32_t sAbase = (uint32_t)__cvta_generic_to_shared(Asm);
    const uint32_t sBbase = (uint32_t)__cvta_generic_to_shared(Bsm);

    // stage = 64 k. A: 128 rows x 64 halves -> 1024 cp16 -> 4/thread.
    auto cp_stage = [&](int s) {
        const int k0 = s << 6;
        const int buf = s % NSTG;
        const uint32_t ab = sAbase + (uint32_t)(buf * A_STG) * 2u;
        #pragma unroll
        for (int i = 0; i < 4; i++) {
            int idx = tid + 256 * i;
            int r = idx >> 3, seg = idx & 7;
            cp16(ab + (uint32_t)(r * APITCH + seg * 8) * 2u,
                 A + (size_t)(rowBase + r) * lda + k0 + seg * 8);
        }
        const uint32_t bb = sBbase + (uint32_t)(buf * B_STG) * 2u;
        if (TRANSB) {
            #pragma unroll
            for (int i = 0; i < 4; i++) {
                int idx = tid + 256 * i;
                int r = idx >> 3, seg = idx & 7;
                cp16(bb + (uint32_t)(r * APITCH + seg * 8) * 2u,
                     B + (size_t)(colBase + r) * ldb + k0 + seg * 8);
            }
        } else {
            // [k][n] layout: 64 k-rows x 128 n halves
            #pragma unroll
            for (int i = 0; i < 4; i++) {
                int idx = tid + 256 * i;
                int kr = idx >> 4, seg = idx & 15;
                cp16(bb + (uint32_t)(kr * BPITCH + seg * 8) * 2u,
                     B + (size_t)(k0 + kr) * ldb + colBase + seg * 8);
            }
        }
    };

    float acc[4][4][4] = {};
    const int nStages = K >> 6;
    cp_stage(0); cp_commit();
    cp_stage(1); cp_commit();

    for (int s = 0; s < nStages; s++) {
        cp_wait<1>();
        __syncthreads();
        if (s + 2 < nStages) cp_stage(s + 2);
        cp_commit();   // always commit (possibly empty) to keep group accounting exact
        const int buf = s % NSTG;
        const uint32_t sAb = sAbase + (uint32_t)(buf * A_STG) * 2u;
        const uint32_t sBb = sBbase + (uint32_t)(buf * B_STG) * 2u;
        #pragma unroll
        for (int ks = 0; ks < 4; ks++) {
            uint32_t af[4][4];
            #pragma unroll
            for (int mt = 0; mt < 4; mt++) {
                const int m0 = warp_m * 64 + mt * 16;
                uint32_t ad = sAb + (uint32_t)((m0 + (lane & 15)) * APITCH
                                   + ks * 16 + ((lane >> 4) & 1) * 8) * 2u;
                ldm_x4(af[mt], ad);
            }
            uint32_t bf[4][2];
            #pragma unroll
            for (int ntp = 0; ntp < 2; ntp++) {
                const int n0 = warp_n * 32 + ntp * 16;
                uint32_t r[4];
                if (TRANSB) {
                    uint32_t bd = sBb + (uint32_t)((n0 + (lane & 15)) * APITCH
                                       + ks * 16 + ((lane >> 4) & 1) * 8) * 2u;
                    ldm_x4(r, bd);
                    bf[2*ntp][0] = r[0]; bf[2*ntp][1] = r[2];
                    bf[2*ntp+1][0] = r[1]; bf[2*ntp+1][1] = r[3];
                } else {
                    uint32_t bd = sBb + (uint32_t)((ks * 16 + (lane & 15)) * BPITCH
                                       + n0 + ((lane >> 4) & 1) * 8) * 2u;
                    ldm_x4_t(r, bd);
                    bf[2*ntp][0] = r[0]; bf[2*ntp][1] = r[1];
                    bf[2*ntp+1][0] = r[2]; bf[2*ntp+1][1] = r[3];
                }
            }
            #pragma unroll
            for (int mt = 0; mt < 4; mt++)
                #pragma unroll
                for (int nt = 0; nt < 4; nt++)
                    mma_f16(acc[mt][nt], af[mt], bf[nt]);
        }
    }

    // Epilogue
    #pragma unroll
    for (int mt = 0; mt < 4; mt++) {
        const int row0 = rowBase + warp_m * 64 + mt * 16 + g;
        #pragma unroll
        for (int nt = 0; nt < 4; nt++) {
            const int col = colBase + warp_n * 32 + nt * 8 + 2 * c;
            float v0 = acc[mt][nt][0] * alpha, v1 = acc[mt][nt][1] * alpha;
            float v2 = acc[mt][nt][2] * alpha, v3 = acc[mt][nt][3] * alpha;
            if (HAS_BIAS) {
                float b0 = bias[col], b1 = bias[col + 1];
                v0 += b0; v1 += b1; v2 += b0; v3 += b1;
            }
            if (HAS_RES) {
                float2 r0 = *(const float2*)(res + (size_t)row0 * ldc + col);
                float2 r1 = *(const float2*)(res + (size_t)(row0 + 8) * ldc + col);
                v0 += r0.x; v1 += r0.y; v2 += r1.x; v3 += r1.y;
            }
            if (OUT_HALF) {
                *(__half2*)(Ch + (size_t)row0 * ldc + col)       = __floats2half2_rn(v0, v1);
                *(__half2*)(Ch + (size_t)(row0 + 8) * ldc + col) = __floats2half2_rn(v2, v3);
            } else {
                *(float2*)(Cf + (size_t)row0 * ldc + col)       = make_float2(v0, v1);
                *(float2*)(Cf + (size_t)(row0 + 8) * ldc + col) = make_float2(v2, v3);
            }
        }
    }
}

// ---------------- weight/bias convert (fp32 -> fp16, concat) ----------------
__global__ void cvt_weights(const float* __restrict__ wq, const float* __restrict__ wk,
                            const float* __restrict__ wv, const float* __restrict__ wp,
                            const float* __restrict__ bq, const float* __restrict__ bk,
                            const float* __restrict__ bv,
                            __half* __restrict__ W, float* __restrict__ Bc) {
    const int j = blockIdx.y;
    const float* src = (j == 0) ? wq : (j == 1) ? wk : (j == 2) ? wv : wp;
    const int i = (blockIdx.x * 256 + threadIdx.x) * 4;
    float4 v = *(const float4*)(src + i);
    __half2* dst = (__half2*)(W + (size_t)j * 262144 + i);
    dst[0] = __floats2half2_rn(v.x, v.y);
    dst[1] = __floats2half2_rn(v.z, v.w);
    if (j < 3 && i < 512) {
        const float* bs = (j == 0) ? bq : (j == 1) ? bk : bv;
        *(float4*)(Bc + j * 512 + i) = *(const float4*)(bs + i);
    }
}

// ---------------- GroupNorm (fp32 in, fp16 out), float4 vectorized ----------------
__global__ void groupnorm_kernel(const float* __restrict__ x,
                                 const float* __restrict__ gamma,
                                 const float* __restrict__ beta,
                                 __half* __restrict__ out) {
    const int b = blockIdx.x >> 5;
    const int g = blockIdx.x & 31;
    const float* xb = x + (size_t)b * 1024 * 512 + g * 16;
    float s1 = 0.f, s2 = 0.f;
    // 1024 rows x 4 float4 = 4096 vec loads, 16 per thread
    for (int i = threadIdx.x; i < 4096; i += 256) {
        int n = i >> 2, q = i & 3;
        float4 v = *(const float4*)(xb + (size_t)n * 512 + q * 4);
        s1 += v.x + v.y + v.z + v.w;
        s2 += v.x * v.x + v.y * v.y + v.z * v.z + v.w * v.w;
    }
    __shared__ float r1[256], r2[256];
    r1[threadIdx.x] = s1; r2[threadIdx.x] = s2;
    __syncthreads();
    for (int off = 128; off > 0; off >>= 1) {
        if (threadIdx.x < off) {
            r1[threadIdx.x] += r1[threadIdx.x + off];
            r2[threadIdx.x] += r2[threadIdx.x + off];
        }
        __syncthreads();
    }
    const float mean = r1[0] * (1.f / 16384.f);
    const float var  = r2[0] * (1.f / 16384.f) - mean * mean;
    const float inv  = rsqrtf(var + 1e-3f);
    __half* ob = out + (size_t)b * 1024 * 512 + g * 16;
    for (int i = threadIdx.x; i < 4096; i += 256) {
        int n = i >> 2, q = i & 3;
        int ch = g * 16 + q * 4;
        float4 v = *(const float4*)(xb + (size_t)n * 512 + q * 4);
        float o0 = (v.x - mean) * inv * gamma[ch + 0] + beta[ch + 0];
        float o1 = (v.y - mean) * inv * gamma[ch + 1] + beta[ch + 1];
        float o2 = (v.z - mean) * inv * gamma[ch + 2] + beta[ch + 2];
        float o3 = (v.w - mean) * inv * gamma[ch + 3] + beta[ch + 3];
        __half2* dst = (__half2*)(ob + (size_t)n * 512 + q * 4);
        dst[0] = __floats2half2_rn(o0, o1);
        dst[1] = __floats2half2_rn(o2, o3);
    }
}

// ---------------- Row softmax 1024 (fp32 in, fp16 out) ----------------
__global__ void softmax1024(const float* __restrict__ S, __half* __restrict__ P) {
    const float* p = S + (size_t)blockIdx.x * 1024;
    __half* o = P + (size_t)blockIdx.x * 1024;
    const int t = threadIdx.x;
    const int w = t >> 5, l = t & 31;
    float4 x4 = ((const float4*)p)[t];
    float m = fmaxf(fmaxf(x4.x, x4.y), fmaxf(x4.z, x4.w));
    __shared__ float red[8];
    #pragma unroll
    for (int off = 16; off > 0; off >>= 1)
        m = fmaxf(m, __shfl_xor_sync(0xffffffffu, m, off));
    if (l == 0) red[w] = m;
    __syncthreads();
    m = red[0];
    #pragma unroll
    for (int i = 1; i < 8; i++) m = fmaxf(m, red[i]);
    x4.x = __expf(x4.x - m); x4.y = __expf(x4.y - m);
    x4.z = __expf(x4.z - m); x4.w = __expf(x4.w - m);
    float sum = x4.x + x4.y + x4.z + x4.w;
    #pragma unroll
    for (int off = 16; off > 0; off >>= 1)
        sum += __shfl_xor_sync(0xffffffffu, sum, off);
    __syncthreads();
    if (l == 0) red[w] = sum;
    __syncthreads();
    sum = 0.f;
    #pragma unroll
    for (int i = 0; i < 8; i++) sum += red[i];
    const float inv = 1.f / sum;
    ((__half2*)o)[2 * t]     = __floats2half2_rn(x4.x * inv, x4.y * inv);
    ((__half2*)o)[2 * t + 1] = __floats2half2_rn(x4.z * inv, x4.w * inv);
}

extern "C" void kernel_launch(void* const* d_in, const int* in_sizes, int n_in,
                              void* d_out, int out_size) {
    const float* x     = (const float*)d_in[0];
    const float* gamma = (const float*)d_in[1];
    const float* beta  = (const float*)d_in[2];
    const float* wq    = (const float*)d_in[3];
    const float* bq    = (const float*)d_in[4];
    const float* wk    = (const float*)d_in[5];
    const float* bk    = (const float*)d_in[6];
    const float* wv    = (const float*)d_in[7];
    const float* bv    = (const float*)d_in[8];
    const float* wp    = (const float*)d_in[9];
    const float* bp    = (const float*)d_in[10];
    float* out = (float*)d_out;

    __half *xn, *W, *qkv, *p, *o;
    float *Bc, *s;
    cudaGetSymbolAddress((void**)&xn,  g_xn);
    cudaGetSymbolAddress((void**)&W,   g_w);
    cudaGetSymbolAddress((void**)&Bc,  g_b);
    cudaGetSymbolAddress((void**)&qkv, g_qkv);
    cudaGetSymbolAddress((void**)&s,   g_s);
    cudaGetSymbolAddress((void**)&p,   g_p);
    cudaGetSymbolAddress((void**)&o,   g_o);

    const int SMEM_NT = NSTG * (A_STG + A_STG) * 2;            // 110592
    const int SMEM_NN = NSTG * (A_STG + 64 * BPITCH) * 2;      // 107520
    cudaFuncSetAttribute(mma_gemm<0,1,0,1>, cudaFuncAttributeMaxDynamicSharedMemorySize, SMEM_NN);
    cudaFuncSetAttribute(mma_gemm<1,0,0,0>, cudaFuncAttributeMaxDynamicSharedMemorySize, SMEM_NT);
    cudaFuncSetAttribute(mma_gemm<0,0,0,1>, cudaFuncAttributeMaxDynamicSharedMemorySize, SMEM_NN);
    cudaFuncSetAttribute(mma_gemm<0,1,1,0>, cudaFuncAttributeMaxDynamicSharedMemorySize, SMEM_NN);

    const float scale = 0.044194173824159216f;  // 512^-0.5
    const size_t sQK = 1024u * 512u;   // 524288
    const size_t sS  = 1024u * 1024u;  // 1048576
    const size_t kOff = 16u * sQK;
    const size_t vOff = 32u * sQK;

    // 0) convert weights/biases to fp16 scratch
    cvt_weights<<<dim3(256, 4), 256>>>(wq, wk, wv, wp, bq, bk, bv, W, Bc);
    // 1) GroupNorm -> fp16 xn
    groupnorm_kernel<<<512, 256>>>(x, gamma, beta, xn);
    // 2) fused Q|K|V projection
    mma_gemm<0,1,0,1><<<dim3(4, 128, 3), 256, SMEM_NN>>>(
        xn, W, Bc, nullptr, qkv, 512, 512, 512, 512, 1.f,
        0, 262144, kOff, 512);
    // 3) scores = scale * Q @ K^T (batched NT, fp32 out)
    mma_gemm<1,0,0,0><<<dim3(8, 8, 16), 256, SMEM_NT>>>(
        qkv, qkv + kOff, nullptr, nullptr, s, 512, 512, 512, 1024, scale,
        sQK, sQK, sS, 0);
    // 4) softmax rows -> fp16 P
    softmax1024<<<16384, 256>>>(s, p);
    // 5) O = P @ V (batched NN, fp16 out)
    mma_gemm<0,0,0,1><<<dim3(4, 8, 16), 256, SMEM_NN>>>(
        p, qkv + vOff, nullptr, nullptr, o, 1024, 1024, 512, 512, 1.f,
        sS, sQK, sQK, 0);
    // 6) out = O @ wp + bp + x (NN + bias + residual, fp32 out)
    mma_gemm<0,1,1,0><<<dim3(4, 128, 1), 256, SMEM_NN>>>(
        o, W + 3u * 262144u, bp, x, out, 512, 512, 512, 512, 1.f,
        0, 0, 0, 0);
}

// round 7
// speedup vs baseline: 7.3727x; 1.0817x over previous
#include <cuda_runtime.h>
#include <cuda_fp16.h>
#include <math.h>
#include <stdint.h>

// Shapes: B=16, N=1024 (32x32), C=512, GROUPS=32
__device__ __half g_xn [16384u*512u];
__device__ __half g_w  [4u*512u*512u];     // wq|wk|wv|wp fp16
__device__ float  g_b  [3u*512u];          // bq|bk|bv
__device__ __half g_qkv[3u*16384u*512u];   // q|k|v
__device__ __half g_p  [16u*1024u*1024u];  // exp(scores) fp16 (unnormalized)
__device__ float  g_rs [16384u];           // per-row sum of exp(scores)
__device__ __half g_o  [16384u*512u];      // attention out fp16

__device__ __forceinline__ void mma_f16(float* d, const uint32_t* a, const uint32_t* b) {
    asm volatile(
        "mma.sync.aligned.m16n8k16.row.col.f32.f16.f16.f32 "
        "{%0,%1,%2,%3}, {%4,%5,%6,%7}, {%8,%9}, {%0,%1,%2,%3};"
        : "+f"(d[0]), "+f"(d[1]), "+f"(d[2]), "+f"(d[3])
        : "r"(a[0]), "r"(a[1]), "r"(a[2]), "r"(a[3]), "r"(b[0]), "r"(b[1]));
}
__device__ __forceinline__ void cp16(uint32_t dst, const void* src) {
    asm volatile("cp.async.cg.shared.global [%0], [%1], 16;" :: "r"(dst), "l"(src));
}
__device__ __forceinline__ void cp_commit() {
    asm volatile("cp.async.commit_group;" ::: "memory");
}
template<int N> __device__ __forceinline__ void cp_wait() {
    asm volatile("cp.async.wait_group %0;" :: "n"(N) : "memory");
}
__device__ __forceinline__ void ldm_x4(uint32_t* r, uint32_t a) {
    asm volatile("ldmatrix.sync.aligned.m8n8.x4.shared.b16 {%0,%1,%2,%3}, [%4];"
                 : "=r"(r[0]), "=r"(r[1]), "=r"(r[2]), "=r"(r[3]) : "r"(a));
}
__device__ __forceinline__ void ldm_x4_t(uint32_t* r, uint32_t a) {
    asm volatile("ldmatrix.sync.aligned.m8n8.x4.trans.shared.b16 {%0,%1,%2,%3}, [%4];"
                 : "=r"(r[0]), "=r"(r[1]), "=r"(r[2]), "=r"(r[3]) : "r"(a));
}

// ---------------- fp16 mma.sync GEMM: 128x128 tile, BK=64, 3-stage cp.async ----------------
// TRANSB=1: B is [N,K] row-major (NT). TRANSB=0: B is [K,N] row-major (NN).
// 256 threads = 8 warps (2m x 4n), warp tile 64x32, m16n8k16.
// EPI: 0 = bias/res options; 1 = exp(alpha*acc) + atomic row-sum (OUT_HALF); 2 = scale by 1/rowsum.
#define APITCH 72
#define BPITCH 136
#define A_STG (128 * APITCH)
#define NSTG 3
template<int TRANSB, int HAS_BIAS, int HAS_RES, int OUT_HALF, int EPI>
__global__ void __launch_bounds__(256, 2) mma_gemm(
    const __half* __restrict__ A, const __half* __restrict__ B,
    const float* __restrict__ bias, const float* __restrict__ res,
    float* __restrict__ rowsum,
    void* __restrict__ Cv, int K, int lda, int ldb, int ldc, float alpha,
    size_t sA, size_t sB, size_t sC, int biasStride)
{
    extern __shared__ __align__(16) __half smem[];
    const int B_STG = TRANSB ? A_STG : (64 * BPITCH);
    __half* Asm = smem;
    __half* Bsm = smem + NSTG * A_STG;

    const int tid  = threadIdx.x;
    const int wid  = tid >> 5;
    const int lane = tid & 31;
    const int g = lane >> 2, c = lane & 3;
    const int warp_m = wid >> 2;
    const int warp_n = wid & 3;
    const int rowBase = blockIdx.y * 128;
    const int colBase = blockIdx.x * 128;
    A += (size_t)blockIdx.z * sA;
    B += (size_t)blockIdx.z * sB;
    if (HAS_BIAS) bias += (size_t)blockIdx.z * biasStride;
    if (EPI) rowsum += (size_t)blockIdx.z * 1024;
    __half* Ch = (__half*)Cv + (size_t)blockIdx.z * sC;
    float*  Cf = (float*)Cv  + (size_t)blockIdx.z * sC;

    const uint32_t sAbase = (uint32_t)__cvta_generic_to_shared(Asm);
    const uint32_t sBbase = (uint32_t)__cvta_generic_to_shared(Bsm);

    // Persistent global src pointers (advance +64 halves per stage)
    const __half* pA[4];
    const __half* pB[4];
    uint32_t aoSm[4], boSm[4];
    {
        #pragma unroll
        for (int i = 0; i < 4; i++) {
            int idx = tid + 256 * i;
            int r = idx >> 3, seg = idx & 7;
            pA[i] = A + (size_t)(rowBase + r) * lda + seg * 8;
            aoSm[i] = (uint32_t)(r * APITCH + seg * 8) * 2u;
            if (TRANSB) {
                pB[i] = B + (size_t)(colBase + r) * ldb + seg * 8;
                boSm[i] = aoSm[i];
            } else {
                int kr = idx >> 4, seg2 = idx & 15;
                pB[i] = B + (size_t)kr * ldb + colBase + seg2 * 8;
                boSm[i] = (uint32_t)(kr * BPITCH + seg2 * 8) * 2u;
            }
        }
    }

    auto cp_stage = [&](int s) {
        const int buf = s % NSTG;
        const uint32_t ab = sAbase + (uint32_t)(buf * A_STG) * 2u;
        const uint32_t bb = sBbase + (uint32_t)(buf * B_STG) * 2u;
        #pragma unroll
        for (int i = 0; i < 4; i++) {
            cp16(ab + aoSm[i], pA[i]);
            pA[i] += 64;
        }
        if (TRANSB) {
            #pragma unroll
            for (int i = 0; i < 4; i++) {
                cp16(bb + boSm[i], pB[i]);
                pB[i] += 64;
            }
        } else {
            #pragma unroll
            for (int i = 0; i < 4; i++) {
                cp16(bb + boSm[i], pB[i]);
                pB[i] += (size_t)64 * ldb;
            }
        }
    };

    // Hoisted ldmatrix lane offsets (bytes)
    uint32_t aOff[4], bOff[2];
    #pragma unroll
    for (int mt = 0; mt < 4; mt++)
        aOff[mt] = (uint32_t)((warp_m * 64 + mt * 16 + (lane & 15)) * APITCH
                   + ((lane >> 4) & 1) * 8) * 2u;
    #pragma unroll
    for (int ntp = 0; ntp < 2; ntp++) {
        if (TRANSB)
            bOff[ntp] = (uint32_t)((warp_n * 32 + ntp * 16 + (lane & 15)) * APITCH
                        + ((lane >> 4) & 1) * 8) * 2u;
        else
            bOff[ntp] = (uint32_t)((lane & 15) * BPITCH + warp_n * 32 + ntp * 16
                        + ((lane >> 4) & 1) * 8) * 2u;
    }

    float acc[4][4][4] = {};
    const int nStages = K >> 6;
    cp_stage(0); cp_commit();
    cp_stage(1); cp_commit();

    for (int s = 0; s < nStages; s++) {
        cp_wait<1>();
        __syncthreads();
        if (s + 2 < nStages) cp_stage(s + 2);
        cp_commit();
        const int buf = s % NSTG;
        const uint32_t sAb = sAbase + (uint32_t)(buf * A_STG) * 2u;
        const uint32_t sBb = sBbase + (uint32_t)(buf * B_STG) * 2u;
        #pragma unroll
        for (int ks = 0; ks < 4; ks++) {
            uint32_t af[4][4];
            #pragma unroll
            for (int mt = 0; mt < 4; mt++)
                ldm_x4(af[mt], sAb + aOff[mt] + ks * 32);
            uint32_t bf[4][2];
            #pragma unroll
            for (int ntp = 0; ntp < 2; ntp++) {
                uint32_t r[4];
                if (TRANSB) {
                    ldm_x4(r, sBb + bOff[ntp] + ks * 32);
                    bf[2*ntp][0] = r[0]; bf[2*ntp][1] = r[2];
                    bf[2*ntp+1][0] = r[1]; bf[2*ntp+1][1] = r[3];
                } else {
                    ldm_x4_t(r, sBb + bOff[ntp] + ks * (16 * BPITCH * 2));
                    bf[2*ntp][0] = r[0]; bf[2*ntp][1] = r[1];
                    bf[2*ntp+1][0] = r[2]; bf[2*ntp+1][1] = r[3];
                }
            }
            #pragma unroll
            for (int mt = 0; mt < 4; mt++)
                #pragma unroll
                for (int nt = 0; nt < 4; nt++)
                    mma_f16(acc[mt][nt], af[mt], bf[nt]);
        }
    }

    // Epilogue
    #pragma unroll
    for (int mt = 0; mt < 4; mt++) {
        const int row0 = rowBase + warp_m * 64 + mt * 16 + g;
        float rp0 = 0.f, rp1 = 0.f;
        float inv0 = 1.f, inv1 = 1.f;
        if (EPI == 2) {
            inv0 = 1.f / rowsum[row0 & 1023];
            inv1 = 1.f / rowsum[(row0 + 8) & 1023];
        }
        #pragma unroll
        for (int nt = 0; nt < 4; nt++) {
            const int col = colBase + warp_n * 32 + nt * 8 + 2 * c;
            float v0 = acc[mt][nt][0] * alpha, v1 = acc[mt][nt][1] * alpha;
            float v2 = acc[mt][nt][2] * alpha, v3 = acc[mt][nt][3] * alpha;
            if (EPI == 1) {
                v0 = __expf(v0); v1 = __expf(v1);
                v2 = __expf(v2); v3 = __expf(v3);
                rp0 += v0 + v1; rp1 += v2 + v3;
            }
            if (EPI == 2) { v0 *= inv0; v1 *= inv0; v2 *= inv1; v3 *= inv1; }
            if (HAS_BIAS) {
                float b0 = bias[col], b1 = bias[col + 1];
                v0 += b0; v1 += b1; v2 += b0; v3 += b1;
            }
            if (HAS_RES) {
                float2 r0 = *(const float2*)(res + (size_t)row0 * ldc + col);
                float2 r1 = *(const float2*)(res + (size_t)(row0 + 8) * ldc + col);
                v0 += r0.x; v1 += r0.y; v2 += r1.x; v3 += r1.y;
            }
            if (OUT_HALF) {
                *(__half2*)(Ch + (size_t)row0 * ldc + col)       = __floats2half2_rn(v0, v1);
                *(__half2*)(Ch + (size_t)(row0 + 8) * ldc + col) = __floats2half2_rn(v2, v3);
            } else {
                *(float2*)(Cf + (size_t)row0 * ldc + col)       = make_float2(v0, v1);
                *(float2*)(Cf + (size_t)(row0 + 8) * ldc + col) = make_float2(v2, v3);
            }
        }
        if (EPI == 1) {
            rp0 += __shfl_xor_sync(0xffffffffu, rp0, 1);
            rp0 += __shfl_xor_sync(0xffffffffu, rp0, 2);
            rp1 += __shfl_xor_sync(0xffffffffu, rp1, 1);
            rp1 += __shfl_xor_sync(0xffffffffu, rp1, 2);
            if (c == 0) {
                atomicAdd(&rowsum[row0 & 1023], rp0);
                atomicAdd(&rowsum[(row0 + 8) & 1023], rp1);
            }
        }
    }
}

// ---------------- weight/bias convert (fp32 -> fp16) + rowsum zero ----------------
__global__ void cvt_weights(const float* __restrict__ wq, const float* __restrict__ wk,
                            const float* __restrict__ wv, const float* __restrict__ wp,
                            const float* __restrict__ bq, const float* __restrict__ bk,
                            const float* __restrict__ bv,
                            __half* __restrict__ W, float* __restrict__ Bc,
                            float* __restrict__ rs) {
    const int j = blockIdx.y;
    const float* src = (j == 0) ? wq : (j == 1) ? wk : (j == 2) ? wv : wp;
    const int i = (blockIdx.x * 256 + threadIdx.x) * 4;
    float4 v = *(const float4*)(src + i);
    __half2* dst = (__half2*)(W + (size_t)j * 262144 + i);
    dst[0] = __floats2half2_rn(v.x, v.y);
    dst[1] = __floats2half2_rn(v.z, v.w);
    if (j < 3 && i < 512) {
        const float* bs = (j == 0) ? bq : (j == 1) ? bk : bv;
        *(float4*)(Bc + j * 512 + i) = *(const float4*)(bs + i);
    }
    if (j == 3 && i < 16384) *(float4*)(rs + i) = make_float4(0.f, 0.f, 0.f, 0.f);
}

// ---------------- GroupNorm (fp32 in, fp16 out), float4 vectorized ----------------
__global__ void groupnorm_kernel(const float* __restrict__ x,
                                 const float* __restrict__ gamma,
                                 const float* __restrict__ beta,
                                 __half* __restrict__ out) {
    const int b = blockIdx.x >> 5;
    const int g = blockIdx.x & 31;
    const float* xb = x + (size_t)b * 1024 * 512 + g * 16;
    float s1 = 0.f, s2 = 0.f;
    for (int i = threadIdx.x; i < 4096; i += 256) {
        int n = i >> 2, q = i & 3;
        float4 v = *(const float4*)(xb + (size_t)n * 512 + q * 4);
        s1 += v.x + v.y + v.z + v.w;
        s2 += v.x * v.x + v.y * v.y + v.z * v.z + v.w * v.w;
    }
    __shared__ float r1[256], r2[256];
    r1[threadIdx.x] = s1; r2[threadIdx.x] = s2;
    __syncthreads();
    for (int off = 128; off > 0; off >>= 1) {
        if (threadIdx.x < off) {
            r1[threadIdx.x] += r1[threadIdx.x + off];
            r2[threadIdx.x] += r2[threadIdx.x + off];
        }
        __syncthreads();
    }
    const float mean = r1[0] * (1.f / 16384.f);
    const float var  = r2[0] * (1.f / 16384.f) - mean * mean;
    const float inv  = rsqrtf(var + 1e-3f);
    __half* ob = out + (size_t)b * 1024 * 512 + g * 16;
    for (int i = threadIdx.x; i < 4096; i += 256) {
        int n = i >> 2, q = i & 3;
        int ch = g * 16 + q * 4;
        float4 v = *(const float4*)(xb + (size_t)n * 512 + q * 4);
        float o0 = (v.x - mean) * inv * gamma[ch + 0] + beta[ch + 0];
        float o1 = (v.y - mean) * inv * gamma[ch + 1] + beta[ch + 1];
        float o2 = (v.z - mean) * inv * gamma[ch + 2] + beta[ch + 2];
        float o3 = (v.w - mean) * inv * gamma[ch + 3] + beta[ch + 3];
        __half2* dst = (__half2*)(ob + (size_t)n * 512 + q * 4);
        dst[0] = __floats2half2_rn(o0, o1);
        dst[1] = __floats2half2_rn(o2, o3);
    }
}

extern "C" void kernel_launch(void* const* d_in, const int* in_sizes, int n_in,
                              void* d_out, int out_size) {
    const float* x     = (const float*)d_in[0];
    const float* gamma = (const float*)d_in[1];
    const float* beta  = (const float*)d_in[2];
    const float* wq    = (const float*)d_in[3];
    const float* bq    = (const float*)d_in[4];
    const float* wk    = (const float*)d_in[5];
    const float* bk    = (const float*)d_in[6];
    const float* wv    = (const float*)d_in[7];
    const float* bv    = (const float*)d_in[8];
    const float* wp    = (const float*)d_in[9];
    const float* bp    = (const float*)d_in[10];
    float* out = (float*)d_out;

    __half *xn, *W, *qkv, *p, *o;
    float *Bc, *rs;
    cudaGetSymbolAddress((void**)&xn,  g_xn);
    cudaGetSymbolAddress((void**)&W,   g_w);
    cudaGetSymbolAddress((void**)&Bc,  g_b);
    cudaGetSymbolAddress((void**)&qkv, g_qkv);
    cudaGetSymbolAddress((void**)&p,   g_p);
    cudaGetSymbolAddress((void**)&rs,  g_rs);
    cudaGetSymbolAddress((void**)&o,   g_o);

    const int SMEM_NT = NSTG * (A_STG + A_STG) * 2;            // 110592
    const int SMEM_NN = NSTG * (A_STG + 64 * BPITCH) * 2;      // 107520
    cudaFuncSetAttribute(mma_gemm<0,1,0,1,0>, cudaFuncAttributeMaxDynamicSharedMemorySize, SMEM_NN);
    cudaFuncSetAttribute(mma_gemm<1,0,0,1,1>, cudaFuncAttributeMaxDynamicSharedMemorySize, SMEM_NT);
    cudaFuncSetAttribute(mma_gemm<0,0,0,1,2>, cudaFuncAttributeMaxDynamicSharedMemorySize, SMEM_NN);
    cudaFuncSetAttribute(mma_gemm<0,1,1,0,0>, cudaFuncAttributeMaxDynamicSharedMemorySize, SMEM_NN);

    const float scale = 0.044194173824159216f;  // 512^-0.5
    const size_t sQK = 1024u * 512u;
    const size_t sS  = 1024u * 1024u;
    const size_t kOff = 16u * sQK;
    const size_t vOff = 32u * sQK;

    // 0) convert weights/biases to fp16, zero rowsums
    cvt_weights<<<dim3(256, 4), 256>>>(wq, wk, wv, wp, bq, bk, bv, W, Bc, rs);
    // 1) GroupNorm -> fp16 xn
    groupnorm_kernel<<<512, 256>>>(x, gamma, beta, xn);
    // 2) fused Q|K|V projection
    mma_gemm<0,1,0,1,0><<<dim3(4, 128, 3), 256, SMEM_NN>>>(
        xn, W, Bc, nullptr, nullptr, qkv, 512, 512, 512, 512, 1.f,
        0, 262144, kOff, 512);
    // 3) P_unnorm = exp(scale * Q @ K^T), rowsum accumulated (batched NT)
    mma_gemm<1,0,0,1,1><<<dim3(8, 8, 16), 256, SMEM_NT>>>(
        qkv, qkv + kOff, nullptr, nullptr, rs, p, 512, 512, 512, 1024, scale,
        sQK, sQK, sS, 0);
    // 4) O = (P_unnorm @ V) / rowsum (batched NN)
    mma_gemm<0,0,0,1,2><<<dim3(4, 8, 16), 256, SMEM_NN>>>(
        p, qkv + vOff, nullptr, nullptr, rs, o, 1024, 1024, 512, 512, 1.f,
        sS, sQK, sQK, 0);
    // 5) out = O @ wp + bp + x (NN + bias + residual, fp32 out)
    mma_gemm<0,1,1,0,0><<<dim3(4, 128, 1), 256, SMEM_NN>>>(
        o, W + 3u * 262144u, bp, x, nullptr, out, 512, 512, 512, 512, 1.f,
        0, 0, 0, 0);
}